// round 15
// baseline (speedup 1.0000x reference)
#include <cuda_runtime.h>
#include <cstdint>

// Fixed problem shapes
#define BB  2
#define CC  4
#define TT  512
#define KVL 1024
#define EE  1024
#define HH  16
#define DHD 64

// Scratch (device globals; no allocation allowed)
__device__ float g_q[(size_t)BB * TT * EE];         // [b,t,e]   (tf32-rounded, pre-scaled by 1/8*log2e)
__device__ float g_k[(size_t)BB * CC * KVL * EE];   // [b,c,k,e] (tf32-rounded)
__device__ float g_v[(size_t)BB * CC * KVL * EE];   // [b,c,k,e] (tf32-rounded)
__device__ float g_attn[(size_t)BB * TT * EE];      // channel-pooled attn out (tf32-rounded)
__device__ float g_part[4][(size_t)BB * TT * EE];   // o_gemm split-K partials
// tf32-pre-rounded (RNA) copies of inputs/weights
__device__ float g_hs [(size_t)BB * TT * EE];
__device__ float g_kvr[(size_t)BB * CC * KVL * EE];
__device__ float g_wq [(size_t)EE * EE];
__device__ float g_wk [(size_t)EE * EE];
__device__ float g_wv [(size_t)EE * EE];
__device__ float g_wo [(size_t)EE * EE];

__device__ __forceinline__ uint32_t tf32r(float x) {
    uint32_t r;
    asm("cvt.rna.tf32.f32 %0, %1;" : "=r"(r) : "f"(x));
    return r;
}
__device__ __forceinline__ uint32_t smem_u32(const void* p) {
    uint32_t a;
    asm("{ .reg .u64 t; cvta.to.shared.u64 t, %1; cvt.u32.u64 %0, t; }" : "=r"(a) : "l"(p));
    return a;
}
__device__ __forceinline__ void mma_tf32(float& c0, float& c1, float& c2, float& c3,
                                         uint32_t a0, uint32_t a1, uint32_t a2, uint32_t a3,
                                         uint32_t b0, uint32_t b1) {
    asm volatile(
        "mma.sync.aligned.m16n8k8.row.col.f32.tf32.tf32.f32 "
        "{%0,%1,%2,%3}, {%4,%5,%6,%7}, {%8,%9}, {%0,%1,%2,%3};"
        : "+f"(c0), "+f"(c1), "+f"(c2), "+f"(c3)
        : "r"(a0), "r"(a1), "r"(a2), "r"(a3), "r"(b0), "r"(b1));
}
#define CP16(dst, src) \
    asm volatile("cp.async.ca.shared.global [%0], [%1], 16;" :: "r"(dst), "l"(src))
#define CP_COMMIT() asm volatile("cp.async.commit_group;" ::: "memory")
#define CP_WAITG(n) asm volatile("cp.async.wait_group %0;" :: "n"(n) : "memory")
#define CP_WAIT1()  asm volatile("cp.async.wait_group 1;" ::: "memory")
#define CP_WAIT0()  asm volatile("cp.async.wait_group 0;" ::: "memory")

// ---------------------------------------------------------------------------
// Pre-round pass (float4, RNA): hs | Wq | Wk | Wv | Wo | kv
// ---------------------------------------------------------------------------
#define F4_HS  (262144)
#define F4_W   (262144)
#define F4_KV  (2097152)
#define F4_TOT (F4_HS + 4 * F4_W + F4_KV)

__global__ __launch_bounds__(256)
void preround(const float4* __restrict__ hs, const float4* __restrict__ kv,
              const float4* __restrict__ Wq, const float4* __restrict__ Wk,
              const float4* __restrict__ Wv, const float4* __restrict__ Wo)
{
    size_t i = (size_t)blockIdx.x * 256 + threadIdx.x;
    if (i >= F4_TOT) return;
    const float4* src;
    float4* dst;
    size_t off;
    if (i < F4_HS)               { src = hs; dst = (float4*)g_hs;  off = i; }
    else if (i < F4_HS + F4_W)   { src = Wq; dst = (float4*)g_wq;  off = i - F4_HS; }
    else if (i < F4_HS + 2*F4_W) { src = Wk; dst = (float4*)g_wk;  off = i - F4_HS - F4_W; }
    else if (i < F4_HS + 3*F4_W) { src = Wv; dst = (float4*)g_wv;  off = i - F4_HS - 2*F4_W; }
    else if (i < F4_HS + 4*F4_W) { src = Wo; dst = (float4*)g_wo;  off = i - F4_HS - 3*F4_W; }
    else                         { src = kv; dst = (float4*)g_kvr; off = i - F4_HS - 4*F4_W; }
    float4 v = src[off];
    v.x = __uint_as_float(tf32r(v.x));
    v.y = __uint_as_float(tf32r(v.y));
    v.z = __uint_as_float(tf32r(v.z));
    v.w = __uint_as_float(tf32r(v.w));
    dst[off] = v;
}

// ---------------------------------------------------------------------------
// Async tf32 GEMM: block 128x128, 128 threads (4 warps, 64x64 warp tile),
// cp.async 3-stage pipeline. k16 split-permutation: MMA0 k={4fc,4fc+1},
// MMA1 k={4fc+2,4fc+3} -> ONE LDS.128 per fragment row serves both MMAs.
// KPAD=16: addr row*16+4fc is bank-conflict-free per quarter-warp.
// MODE 0/1/2 -> g_q/g_k/g_v (tf32-rounded, (acc+bias)*scale).
// MODE 3 -> OutP raw fp32 acc (split-K partial).
// ---------------------------------------------------------------------------
#define KPAD 16
#define AOFS (128 * KPAD)
#define STGW (2 * AOFS)
#define GEMM_SMEM (3 * STGW * 4)       // 49152 B

template <int MODE>
__device__ __forceinline__
void gemm_async(const float* __restrict__ Ag, const float* __restrict__ Bg,
                const float* __restrict__ bias, float* __restrict__ OutP,
                float scale, int bm, int bn, float* sm, int stage0, int ns)
{
    const int tid  = threadIdx.x;
    const int lane = tid & 31, warp = tid >> 5;
    const int wm = (warp & 1) * 64;
    const int wn = (warp >> 1) * 64;
    const int fr = lane >> 2, fc = lane & 3;

    const float* Ab0 = Ag + (size_t)(bm * 128) * EE;
    const float* Bb0 = Bg + (size_t)(bn * 128) * EE;
    const uint32_t sb = smem_u32(sm);

    auto issue = [&](int st, int buf) {
        const uint32_t ab = sb + buf * (STGW * 4);
        const uint32_t bbx = ab + AOFS * 4;
#pragma unroll
        for (int it = 0; it < 4; it++) {
            const int lin = it * 128 + tid;
            const int row = lin >> 2, cq = (lin & 3) * 4;
            const uint32_t so = (row * KPAD + cq) * 4;
            CP16(ab + so, Ab0 + (size_t)row * EE + (stage0 + st) * 16 + cq);
            CP16(bbx + so, Bb0 + (size_t)row * EE + (stage0 + st) * 16 + cq);
        }
    };

    float acc[4][8][4];
#pragma unroll
    for (int i = 0; i < 4; i++)
#pragma unroll
        for (int j = 0; j < 8; j++)
#pragma unroll
            for (int r = 0; r < 4; r++) acc[i][j][r] = 0.f;

    issue(0, 0); CP_COMMIT();
    issue(1, 1); CP_COMMIT();

    for (int s = 0; s < ns; s++) {
        CP_WAITG(1);
        __syncthreads();
        if (s + 2 < ns) { issue(s + 2, (s + 2) % 3); }
        CP_COMMIT();

        const float* Abuf = sm + (s % 3) * STGW;
        const float* Bbuf = Abuf + AOFS;

        float4 aA[4][2], bB[8];
#pragma unroll
        for (int mf = 0; mf < 4; mf++) {
            const float* p = Abuf + (wm + mf * 16 + fr) * KPAD + 4 * fc;
            aA[mf][0] = *(const float4*)(p);
            aA[mf][1] = *(const float4*)(p + 8 * KPAD);
        }
#pragma unroll
        for (int nf = 0; nf < 8; nf++)
            bB[nf] = *(const float4*)(Bbuf + (wn + nf * 8 + fr) * KPAD + 4 * fc);

#pragma unroll
        for (int mf = 0; mf < 4; mf++)
#pragma unroll
            for (int nf = 0; nf < 8; nf++)
                mma_tf32(acc[mf][nf][0], acc[mf][nf][1], acc[mf][nf][2], acc[mf][nf][3],
                         __float_as_uint(aA[mf][0].x), __float_as_uint(aA[mf][1].x),
                         __float_as_uint(aA[mf][0].y), __float_as_uint(aA[mf][1].y),
                         __float_as_uint(bB[nf].x), __float_as_uint(bB[nf].y));
#pragma unroll
        for (int mf = 0; mf < 4; mf++)
#pragma unroll
            for (int nf = 0; nf < 8; nf++)
                mma_tf32(acc[mf][nf][0], acc[mf][nf][1], acc[mf][nf][2], acc[mf][nf][3],
                         __float_as_uint(aA[mf][0].z), __float_as_uint(aA[mf][1].z),
                         __float_as_uint(aA[mf][0].w), __float_as_uint(aA[mf][1].w),
                         __float_as_uint(bB[nf].z), __float_as_uint(bB[nf].w));
    }

    float* Out = (MODE == 0) ? g_q : (MODE == 1) ? g_k : (MODE == 2) ? g_v : OutP;
#pragma unroll
    for (int nf = 0; nf < 8; nf++) {
        const int n0 = bn * 128 + wn + nf * 8 + fc * 2;
        float2 b2 = make_float2(0.f, 0.f);
        if (MODE != 3) b2 = *(const float2*)(bias + n0);
#pragma unroll
        for (int mf = 0; mf < 4; mf++) {
            const int m0 = bm * 128 + wm + mf * 16 + fr;
            float2 v0, v1;
            if (MODE == 3) {
                v0.x = acc[mf][nf][0];
                v0.y = acc[mf][nf][1];
                v1.x = acc[mf][nf][2];
                v1.y = acc[mf][nf][3];
            } else {
                v0.x = __uint_as_float(tf32r((acc[mf][nf][0] + b2.x) * scale));
                v0.y = __uint_as_float(tf32r((acc[mf][nf][1] + b2.y) * scale));
                v1.x = __uint_as_float(tf32r((acc[mf][nf][2] + b2.x) * scale));
                v1.y = __uint_as_float(tf32r((acc[mf][nf][3] + b2.y) * scale));
            }
            *(float2*)(Out + (size_t)m0 * EE + n0) = v0;
            *(float2*)(Out + (size_t)(m0 + 8) * EE + n0) = v1;
        }
    }
}

// blocks: 0..63 Q (8x8), 64..575 K (64x8), 576..1087 V
// Q scale folds Dh^-0.5 AND log2e (softmax runs in log2 domain).
#define QSCALE (0.125f * 1.44269504f)

__global__ __launch_bounds__(128, 2)
void qkv_gemm(const float* __restrict__ bq, const float* __restrict__ bk,
              const float* __restrict__ bv)
{
    extern __shared__ float sm[];
    const int blk = blockIdx.x;
    if (blk < 64) {
        gemm_async<0>(g_hs, g_wq, bq, nullptr, QSCALE, blk >> 3, blk & 7, sm, 0, 64);
    } else if (blk < 576) {
        const int i = blk - 64;
        gemm_async<1>(g_kvr, g_wk, bk, nullptr, 1.f, i >> 3, i & 7, sm, 0, 64);
    } else {
        const int i = blk - 576;
        gemm_async<2>(g_kvr, g_wv, bv, nullptr, 1.f, i >> 3, i & 7, sm, 0, 64);
    }
}

// Split-K x4 output projection: z = K-split, 16 stages each -> g_part[z]
__global__ __launch_bounds__(128, 2)
void o_gemm()
{
    extern __shared__ float sm[];
    const int z = blockIdx.z;
    gemm_async<3>(g_attn, g_wo, nullptr, g_part[z], 1.f,
                  blockIdx.y, blockIdx.x, sm, z * 16, 16);
}

// out = sum_z g_part[z] + bias  (deterministic fixed-order reduce)
__global__ __launch_bounds__(256)
void o_reduce(const float* __restrict__ bo, float4* __restrict__ out)
{
    const size_t i = (size_t)blockIdx.x * 256 + threadIdx.x;   // float4 index
    if (i >= (size_t)BB * TT * EE / 4) return;
    float4 p0 = ((const float4*)g_part[0])[i];
    float4 p1 = ((const float4*)g_part[1])[i];
    float4 p2 = ((const float4*)g_part[2])[i];
    float4 p3 = ((const float4*)g_part[3])[i];
    const float4 b4 = *(const float4*)(bo + (i % (EE / 4)) * 4);
    float4 v;
    v.x = p0.x + p1.x + p2.x + p3.x + b4.x;
    v.y = p0.y + p1.y + p2.y + p3.y + b4.y;
    v.z = p0.z + p1.z + p2.z + p3.z + b4.z;
    v.w = p0.w + p1.w + p2.w + p3.w + b4.w;
    out[i] = v;
}

// ---------------------------------------------------------------------------
// mma.sync tf32 flash attention, fused channel pooling.
// Block = (t-tile 64, b*H+h); 128 threads = 4 warps x 16 t-rows.
// Grid 256 -> 2 CTAs/SM co-resident (smem 105 KB each): the second CTA's
// warps hide the first's cp.async-wait and barrier stalls.
// 64 flattened kv-chunks (channel = g>>4), 3-stage cp.async pipeline,
// one barrier per chunk. Log2-domain max-free softmax (Q pre-scaled).
// QK: k-perm {2fc,2fc+1}, K LDS.64, KSTR=72 (conflict-free).
// PV: S accumulator IS the A fragment; V stride 68.
// ---------------------------------------------------------------------------
#define KSTR  72
#define VSTR  68
#define KSW   (64 * KSTR)
#define VSW   (64 * VSTR)
#define ASTG  (KSW + VSW)                 // 8960 words
#define ATTN_SMEM (3 * ASTG * 4)          // 107520 B per CTA

__global__ __launch_bounds__(128, 2)
void attn_kernel()
{
    extern __shared__ float sm[];
    const uint32_t sb = smem_u32(sm);

    const int tid = threadIdx.x;
    const int lane = tid & 31, w = tid >> 5;          // 4 warps
    const int fr = lane >> 2, fc = lane & 3;
    const int t0 = blockIdx.x << 6;                    // t-tile 64
    const int bh = blockIdx.y;
    const int b = bh >> 4, h = bh & 15;

    const float* qg  = g_q + ((size_t)b * TT + t0) * EE + h * DHD;
    const float* kg0 = g_k + ((size_t)b * CC * KVL) * EE + h * DHD;
    const float* vg0 = g_v + ((size_t)b * CC * KVL) * EE + h * DHD;

    // Loader: 128 threads, 64x64 tile: thread covers row tid>>1, 32 floats
    const int lrow = tid >> 1;
    const int lcq  = (tid & 1) << 5;                   // 0 or 32
    const uint32_t kdst0 = sb + (lrow * KSTR + lcq) * 4;
    const uint32_t vdst0 = sb + (KSW + lrow * VSTR + lcq) * 4;

    auto issue = [&](int g, int buf) {
        const size_t roff = ((size_t)(g >> 4) * KVL + (g & 15) * 64 + lrow) * EE + lcq;
        const uint32_t kd = kdst0 + buf * (ASTG * 4);
        const uint32_t vd = vdst0 + buf * (ASTG * 4);
#pragma unroll
        for (int u = 0; u < 8; u++) {
            CP16(kd + u * 16, kg0 + roff + 4 * u);
            CP16(vd + u * 16, vg0 + roff + 4 * u);
        }
    };

    issue(0, 0); CP_COMMIT();
    issue(1, 1); CP_COMMIT();

    // Q fragments, k-perm: physical d {2fc, 2fc+1} per k8 step
    uint32_t qa[8][4];
    {
        const float* q0 = qg + (size_t)(16 * w + fr) * EE;
#pragma unroll
        for (int k = 0; k < 8; k++) {
            qa[k][0] = __float_as_uint(q0[8 * k + 2 * fc]);
            qa[k][2] = __float_as_uint(q0[8 * k + 2 * fc + 1]);
            qa[k][1] = __float_as_uint(q0[8 * (size_t)EE + 8 * k + 2 * fc]);
            qa[k][3] = __float_as_uint(q0[8 * (size_t)EE + 8 * k + 2 * fc + 1]);
        }
    }

    float at[8][4];
    float o[8][4];
#pragma unroll
    for (int n = 0; n < 8; n++)
#pragma unroll
        for (int r = 0; r < 4; r++) at[n][r] = 0.f;
    float l0r = 0.f, l1r = 0.f;

    for (int g = 0; g < 64; g++) {
        if ((g & 15) == 0) {
            l0r = 0.f; l1r = 0.f;
#pragma unroll
            for (int n = 0; n < 8; n++)
#pragma unroll
                for (int r = 0; r < 4; r++) o[n][r] = 0.f;
        }
        if (g == 63) { CP_WAIT0(); } else { CP_WAIT1(); }
        __syncthreads();
        if (g + 2 < 64) { issue(g + 2, (g + 2) % 3); CP_COMMIT(); }

        const float* Kb = sm + (g % 3) * ASTG;
        const float* Vb = Kb + KSW;

        float s[8][4];
#pragma unroll
        for (int n = 0; n < 8; n++)
#pragma unroll
            for (int r = 0; r < 4; r++) s[n][r] = 0.f;

        // S = Q K^T : K B-fragment pairs adjacent -> LDS.64
        const int kb0 = fr * KSTR + 2 * fc;
#pragma unroll
        for (int kk = 0; kk < 8; kk++) {
#pragma unroll
            for (int nf = 0; nf < 8; nf++) {
                float2 b01 = *(const float2*)(Kb + nf * (8 * KSTR) + kk * 8 + kb0);
                mma_tf32(s[nf][0], s[nf][1], s[nf][2], s[nf][3],
                         qa[kk][0], qa[kk][1], qa[kk][2], qa[kk][3],
                         __float_as_uint(b01.x), __float_as_uint(b01.y));
            }
        }

        // Max-free softmax in log2 domain: p = 2^s
        float sum0 = 0.f, sum1 = 0.f;
#pragma unroll
        for (int n = 0; n < 8; n++) {
            s[n][0] = exp2f(s[n][0]);
            s[n][1] = exp2f(s[n][1]);
            s[n][2] = exp2f(s[n][2]);
            s[n][3] = exp2f(s[n][3]);
            sum0 += s[n][0] + s[n][1];
            sum1 += s[n][2] + s[n][3];
        }
        sum0 += __shfl_xor_sync(0xffffffffu, sum0, 1);
        sum0 += __shfl_xor_sync(0xffffffffu, sum0, 2);
        sum1 += __shfl_xor_sync(0xffffffffu, sum1, 1);
        sum1 += __shfl_xor_sync(0xffffffffu, sum1, 2);
        l0r += sum0;
        l1r += sum1;

        // O += P V : accumulator fragment IS the A fragment (k {2fc,2fc+1})
        const int vb0 = 2 * fc * VSTR + fr;
#pragma unroll
        for (int j = 0; j < 8; j++) {
            const uint32_t a0 = tf32r(s[j][0]);
            const uint32_t a1 = tf32r(s[j][2]);
            const uint32_t a2 = tf32r(s[j][1]);
            const uint32_t a3 = tf32r(s[j][3]);
            const float* vp = Vb + j * (8 * VSTR) + vb0;
#pragma unroll
            for (int nf = 0; nf < 8; nf++) {
                mma_tf32(o[nf][0], o[nf][1], o[nf][2], o[nf][3],
                         a0, a1, a2, a3,
                         __float_as_uint(vp[8 * nf]), __float_as_uint(vp[VSTR + 8 * nf]));
            }
        }

        if ((g & 15) == 15) {
            const float inv0 = 0.25f / l0r;
            const float inv1 = 0.25f / l1r;
#pragma unroll
            for (int n = 0; n < 8; n++) {
                at[n][0] += o[n][0] * inv0;
                at[n][1] += o[n][1] * inv0;
                at[n][2] += o[n][2] * inv1;
                at[n][3] += o[n][3] * inv1;
            }
        }
    }

    // Write tf32-rounded (RNA) channel-pooled output (A operand of o_gemm)
    float* op = g_attn + (size_t)(b * TT + t0 + 16 * w + fr) * EE + h * DHD + 2 * fc;
#pragma unroll
    for (int nf = 0; nf < 8; nf++) {
        float2 v0, v1;
        v0.x = __uint_as_float(tf32r(at[nf][0]));
        v0.y = __uint_as_float(tf32r(at[nf][1]));
        v1.x = __uint_as_float(tf32r(at[nf][2]));
        v1.y = __uint_as_float(tf32r(at[nf][3]));
        *(float2*)(op + 8 * nf) = v0;
        *(float2*)(op + 8 * (size_t)EE + 8 * nf) = v1;
    }
}

// ---------------------------------------------------------------------------
extern "C" void kernel_launch(void* const* d_in, const int* in_sizes, int n_in,
                              void* d_out, int out_size)
{
    const float* hs = (const float*)d_in[0];
    const float* kv = (const float*)d_in[1];
    const float* Wq = (const float*)d_in[2];
    const float* bq = (const float*)d_in[3];
    const float* Wk = (const float*)d_in[4];
    const float* bk = (const float*)d_in[5];
    const float* Wv = (const float*)d_in[6];
    const float* bv = (const float*)d_in[7];
    const float* Wo = (const float*)d_in[8];
    const float* bo = (const float*)d_in[9];
    float* out = (float*)d_out;

    cudaFuncSetAttribute(qkv_gemm, cudaFuncAttributeMaxDynamicSharedMemorySize, GEMM_SMEM);
    cudaFuncSetAttribute(o_gemm, cudaFuncAttributeMaxDynamicSharedMemorySize, GEMM_SMEM);
    cudaFuncSetAttribute(attn_kernel, cudaFuncAttributeMaxDynamicSharedMemorySize, ATTN_SMEM);

    // tf32 (RNA) pre-rounding of inputs + weights
    preround<<<(F4_TOT + 255) / 256, 256>>>((const float4*)hs, (const float4*)kv,
                                            (const float4*)Wq, (const float4*)Wk,
                                            (const float4*)Wv, (const float4*)Wo);
    // Fused Q+K+V projections (Q scaled by Dh^-0.5 * log2e)
    qkv_gemm<<<1088, 128, GEMM_SMEM>>>(bq, bk, bv);
    // Flash attention with fused channel pooling -> g_attn
    attn_kernel<<<dim3(TT / 64, BB * HH), 128, ATTN_SMEM>>>();
    // Output projection: split-K x4 partials, then deterministic reduce + bias
    o_gemm<<<dim3(8, 8, 4), 128, GEMM_SMEM>>>();
    o_reduce<<<(BB * TT * EE / 4 + 255) / 256, 256>>>(bo, (float4*)out);
}

// round 16
// speedup vs baseline: 1.4123x; 1.4123x over previous
#include <cuda_runtime.h>
#include <cstdint>

// Fixed problem shapes
#define BB  2
#define CC  4
#define TT  512
#define KVL 1024
#define EE  1024
#define HH  16
#define DHD 64

// Scratch (device globals; no allocation allowed)
__device__ float g_q[(size_t)BB * TT * EE];         // [b,t,e]   (tf32-rounded, pre-scaled by 1/8*log2e)
__device__ float g_k[(size_t)BB * CC * KVL * EE];   // [b,c,k,e] (tf32-rounded)
__device__ float g_v[(size_t)BB * CC * KVL * EE];   // [b,c,k,e] (tf32-rounded)
__device__ float g_attn[(size_t)BB * TT * EE];      // channel-pooled attn out (tf32-rounded)
__device__ float g_part[4][(size_t)BB * TT * EE];   // o_gemm split-K partials
// tf32-pre-rounded (RNA) copies of inputs/weights
__device__ float g_hs [(size_t)BB * TT * EE];
__device__ float g_kvr[(size_t)BB * CC * KVL * EE];
__device__ float g_wq [(size_t)EE * EE];
__device__ float g_wk [(size_t)EE * EE];
__device__ float g_wv [(size_t)EE * EE];
__device__ float g_wo [(size_t)EE * EE];

__device__ __forceinline__ uint32_t tf32r(float x) {
    uint32_t r;
    asm("cvt.rna.tf32.f32 %0, %1;" : "=r"(r) : "f"(x));
    return r;
}
__device__ __forceinline__ uint32_t smem_u32(const void* p) {
    uint32_t a;
    asm("{ .reg .u64 t; cvta.to.shared.u64 t, %1; cvt.u32.u64 %0, t; }" : "=r"(a) : "l"(p));
    return a;
}
__device__ __forceinline__ void mma_tf32(float& c0, float& c1, float& c2, float& c3,
                                         uint32_t a0, uint32_t a1, uint32_t a2, uint32_t a3,
                                         uint32_t b0, uint32_t b1) {
    asm volatile(
        "mma.sync.aligned.m16n8k8.row.col.f32.tf32.tf32.f32 "
        "{%0,%1,%2,%3}, {%4,%5,%6,%7}, {%8,%9}, {%0,%1,%2,%3};"
        : "+f"(c0), "+f"(c1), "+f"(c2), "+f"(c3)
        : "r"(a0), "r"(a1), "r"(a2), "r"(a3), "r"(b0), "r"(b1));
}
#define CP16(dst, src) \
    asm volatile("cp.async.ca.shared.global [%0], [%1], 16;" :: "r"(dst), "l"(src))
#define CP_COMMIT() asm volatile("cp.async.commit_group;" ::: "memory")
#define CP_WAITG(n) asm volatile("cp.async.wait_group %0;" :: "n"(n) : "memory")
#define CP_WAIT1()  asm volatile("cp.async.wait_group 1;" ::: "memory")
#define CP_WAIT0()  asm volatile("cp.async.wait_group 0;" ::: "memory")

// ---------------------------------------------------------------------------
// Pre-round pass (float4, RNA): hs | Wq | Wk | Wv | Wo | kv
// ---------------------------------------------------------------------------
#define F4_HS  (262144)
#define F4_W   (262144)
#define F4_KV  (2097152)
#define F4_TOT (F4_HS + 4 * F4_W + F4_KV)

__global__ __launch_bounds__(256)
void preround(const float4* __restrict__ hs, const float4* __restrict__ kv,
              const float4* __restrict__ Wq, const float4* __restrict__ Wk,
              const float4* __restrict__ Wv, const float4* __restrict__ Wo)
{
    size_t i = (size_t)blockIdx.x * 256 + threadIdx.x;
    if (i >= F4_TOT) return;
    const float4* src;
    float4* dst;
    size_t off;
    if (i < F4_HS)               { src = hs; dst = (float4*)g_hs;  off = i; }
    else if (i < F4_HS + F4_W)   { src = Wq; dst = (float4*)g_wq;  off = i - F4_HS; }
    else if (i < F4_HS + 2*F4_W) { src = Wk; dst = (float4*)g_wk;  off = i - F4_HS - F4_W; }
    else if (i < F4_HS + 3*F4_W) { src = Wv; dst = (float4*)g_wv;  off = i - F4_HS - 2*F4_W; }
    else if (i < F4_HS + 4*F4_W) { src = Wo; dst = (float4*)g_wo;  off = i - F4_HS - 3*F4_W; }
    else                         { src = kv; dst = (float4*)g_kvr; off = i - F4_HS - 4*F4_W; }
    float4 v = src[off];
    v.x = __uint_as_float(tf32r(v.x));
    v.y = __uint_as_float(tf32r(v.y));
    v.z = __uint_as_float(tf32r(v.z));
    v.w = __uint_as_float(tf32r(v.w));
    dst[off] = v;
}

// ---------------------------------------------------------------------------
// Async tf32 GEMM: block 128x128, 128 threads (4 warps, 64x64 warp tile),
// cp.async 4-stage pipeline (lookahead 3). k16 split-permutation: MMA0
// k={4fc,4fc+1}, MMA1 k={4fc+2,4fc+3} -> one LDS.128 per fragment row.
// KPAD=16: addr row*16+4fc is bank-conflict-free per quarter-warp.
// MODE 0/1/2 -> g_q/g_k/g_v (tf32-rounded, (acc+bias)*scale).
// MODE 3 -> OutP raw fp32 acc (split-K partial).
// ---------------------------------------------------------------------------
#define KPAD 16
#define AOFS (128 * KPAD)
#define STGW (2 * AOFS)
#define GEMM_SMEM (4 * STGW * 4)       // 65536 B

template <int MODE>
__device__ __forceinline__
void gemm_async(const float* __restrict__ Ag, const float* __restrict__ Bg,
                const float* __restrict__ bias, float* __restrict__ OutP,
                float scale, int bm, int bn, float* sm, int stage0, int ns)
{
    const int tid  = threadIdx.x;
    const int lane = tid & 31, warp = tid >> 5;
    const int wm = (warp & 1) * 64;
    const int wn = (warp >> 1) * 64;
    const int fr = lane >> 2, fc = lane & 3;

    const float* Ab0 = Ag + (size_t)(bm * 128) * EE;
    const float* Bb0 = Bg + (size_t)(bn * 128) * EE;
    const uint32_t sb = smem_u32(sm);

    auto issue = [&](int st, int buf) {
        const uint32_t ab = sb + buf * (STGW * 4);
        const uint32_t bbx = ab + AOFS * 4;
#pragma unroll
        for (int it = 0; it < 4; it++) {
            const int lin = it * 128 + tid;
            const int row = lin >> 2, cq = (lin & 3) * 4;
            const uint32_t so = (row * KPAD + cq) * 4;
            CP16(ab + so, Ab0 + (size_t)row * EE + (stage0 + st) * 16 + cq);
            CP16(bbx + so, Bb0 + (size_t)row * EE + (stage0 + st) * 16 + cq);
        }
    };

    float acc[4][8][4];
#pragma unroll
    for (int i = 0; i < 4; i++)
#pragma unroll
        for (int j = 0; j < 8; j++)
#pragma unroll
            for (int r = 0; r < 4; r++) acc[i][j][r] = 0.f;

    issue(0, 0); CP_COMMIT();
    issue(1, 1); CP_COMMIT();
    issue(2, 2); CP_COMMIT();

    for (int s = 0; s < ns; s++) {
        // committed groups so far = min(s+3, ns); need group s complete
        if (s >= ns - 1)      { CP_WAIT0(); }
        else if (s == ns - 2) { CP_WAIT1(); }
        else                  { CP_WAITG(2); }
        __syncthreads();
        if (s + 3 < ns) { issue(s + 3, (s + 3) & 3); }
        CP_COMMIT();

        const float* Abuf = sm + (s & 3) * STGW;
        const float* Bbuf = Abuf + AOFS;

        float4 aA[4][2], bB[8];
#pragma unroll
        for (int mf = 0; mf < 4; mf++) {
            const float* p = Abuf + (wm + mf * 16 + fr) * KPAD + 4 * fc;
            aA[mf][0] = *(const float4*)(p);
            aA[mf][1] = *(const float4*)(p + 8 * KPAD);
        }
#pragma unroll
        for (int nf = 0; nf < 8; nf++)
            bB[nf] = *(const float4*)(Bbuf + (wn + nf * 8 + fr) * KPAD + 4 * fc);

#pragma unroll
        for (int mf = 0; mf < 4; mf++)
#pragma unroll
            for (int nf = 0; nf < 8; nf++)
                mma_tf32(acc[mf][nf][0], acc[mf][nf][1], acc[mf][nf][2], acc[mf][nf][3],
                         __float_as_uint(aA[mf][0].x), __float_as_uint(aA[mf][1].x),
                         __float_as_uint(aA[mf][0].y), __float_as_uint(aA[mf][1].y),
                         __float_as_uint(bB[nf].x), __float_as_uint(bB[nf].y));
#pragma unroll
        for (int mf = 0; mf < 4; mf++)
#pragma unroll
            for (int nf = 0; nf < 8; nf++)
                mma_tf32(acc[mf][nf][0], acc[mf][nf][1], acc[mf][nf][2], acc[mf][nf][3],
                         __float_as_uint(aA[mf][0].z), __float_as_uint(aA[mf][1].z),
                         __float_as_uint(aA[mf][0].w), __float_as_uint(aA[mf][1].w),
                         __float_as_uint(bB[nf].z), __float_as_uint(bB[nf].w));
    }

    float* Out = (MODE == 0) ? g_q : (MODE == 1) ? g_k : (MODE == 2) ? g_v : OutP;
#pragma unroll
    for (int nf = 0; nf < 8; nf++) {
        const int n0 = bn * 128 + wn + nf * 8 + fc * 2;
        float2 b2 = make_float2(0.f, 0.f);
        if (MODE != 3) b2 = *(const float2*)(bias + n0);
#pragma unroll
        for (int mf = 0; mf < 4; mf++) {
            const int m0 = bm * 128 + wm + mf * 16 + fr;
            float2 v0, v1;
            if (MODE == 3) {
                v0.x = acc[mf][nf][0];
                v0.y = acc[mf][nf][1];
                v1.x = acc[mf][nf][2];
                v1.y = acc[mf][nf][3];
            } else {
                v0.x = __uint_as_float(tf32r((acc[mf][nf][0] + b2.x) * scale));
                v0.y = __uint_as_float(tf32r((acc[mf][nf][1] + b2.y) * scale));
                v1.x = __uint_as_float(tf32r((acc[mf][nf][2] + b2.x) * scale));
                v1.y = __uint_as_float(tf32r((acc[mf][nf][3] + b2.y) * scale));
            }
            *(float2*)(Out + (size_t)m0 * EE + n0) = v0;
            *(float2*)(Out + (size_t)(m0 + 8) * EE + n0) = v1;
        }
    }
}

// blocks: 0..63 Q (8x8), 64..575 K (64x8), 576..1087 V
// Q scale folds Dh^-0.5 AND log2e (softmax runs in log2 domain).
#define QSCALE (0.125f * 1.44269504f)

__global__ __launch_bounds__(128, 2)
void qkv_gemm(const float* __restrict__ bq, const float* __restrict__ bk,
              const float* __restrict__ bv)
{
    extern __shared__ float sm[];
    const int blk = blockIdx.x;
    if (blk < 64) {
        gemm_async<0>(g_hs, g_wq, bq, nullptr, QSCALE, blk >> 3, blk & 7, sm, 0, 64);
    } else if (blk < 576) {
        const int i = blk - 64;
        gemm_async<1>(g_kvr, g_wk, bk, nullptr, 1.f, i >> 3, i & 7, sm, 0, 64);
    } else {
        const int i = blk - 576;
        gemm_async<2>(g_kvr, g_wv, bv, nullptr, 1.f, i >> 3, i & 7, sm, 0, 64);
    }
}

// Split-K x4 output projection: z = K-split, 16 stages each -> g_part[z]
__global__ __launch_bounds__(128, 2)
void o_gemm()
{
    extern __shared__ float sm[];
    const int z = blockIdx.z;
    gemm_async<3>(g_attn, g_wo, nullptr, g_part[z], 1.f,
                  blockIdx.y, blockIdx.x, sm, z * 16, 16);
}

// out = sum_z g_part[z] + bias  (deterministic fixed-order reduce)
__global__ __launch_bounds__(256)
void o_reduce(const float* __restrict__ bo, float4* __restrict__ out)
{
    const size_t i = (size_t)blockIdx.x * 256 + threadIdx.x;   // float4 index
    if (i >= (size_t)BB * TT * EE / 4) return;
    float4 p0 = ((const float4*)g_part[0])[i];
    float4 p1 = ((const float4*)g_part[1])[i];
    float4 p2 = ((const float4*)g_part[2])[i];
    float4 p3 = ((const float4*)g_part[3])[i];
    const float4 b4 = *(const float4*)(bo + (i % (EE / 4)) * 4);
    float4 v;
    v.x = p0.x + p1.x + p2.x + p3.x + b4.x;
    v.y = p0.y + p1.y + p2.y + p3.y + b4.y;
    v.z = p0.z + p1.z + p2.z + p3.z + b4.z;
    v.w = p0.w + p1.w + p2.w + p3.w + b4.w;
    out[i] = v;
}

// ---------------------------------------------------------------------------
// mma.sync tf32 flash attention, fused channel pooling (round-14 proven).
// Block = (t-tile 128, b*H+h); 8 warps x 16 t-rows; 64 flattened kv-chunks
// (channel = g>>4). 3-stage cp.async pipeline, one barrier per chunk.
// QK uses the k16 split-permutation (one LDS.128 per (nf, d-group) -> 2 MMAs),
// KSTR=80 conflict-free. Log2-domain max-free softmax (Q pre-scaled).
// PV: S accumulator IS the A fragment (k-perm {2fc,2fc+1}); V stride 68.
// ---------------------------------------------------------------------------
#define KSTR  80
#define VSTR  68
#define KSW   (64 * KSTR)
#define VSW   (64 * VSTR)
#define ASTG  (KSW + VSW)                 // 9472 words
#define ATTN_SMEM (3 * ASTG * 4)          // 113664 B

__global__ __launch_bounds__(256)
void attn_kernel()
{
    extern __shared__ float sm[];
    const uint32_t sb = smem_u32(sm);

    const int tid = threadIdx.x;
    const int lane = tid & 31, w = tid >> 5;
    const int fr = lane >> 2, fc = lane & 3;
    const int t0 = blockIdx.x << 7;
    const int bh = blockIdx.y;
    const int b = bh >> 4, h = bh & 15;

    const float* qg  = g_q + ((size_t)b * TT + t0) * EE + h * DHD;
    const float* kg0 = g_k + ((size_t)b * CC * KVL) * EE + h * DHD;
    const float* vg0 = g_v + ((size_t)b * CC * KVL) * EE + h * DHD;

    const int lrow = tid >> 2;
    const int lcq  = (tid & 3) << 4;
    const uint32_t kdst0 = sb + (lrow * KSTR + lcq) * 4;
    const uint32_t vdst0 = sb + (KSW + lrow * VSTR + lcq) * 4;

    auto issue = [&](int g, int buf) {
        const size_t roff = ((size_t)(g >> 4) * KVL + (g & 15) * 64 + lrow) * EE + lcq;
        const uint32_t kd = kdst0 + buf * (ASTG * 4);
        const uint32_t vd = vdst0 + buf * (ASTG * 4);
#pragma unroll
        for (int u = 0; u < 4; u++) {
            CP16(kd + u * 16, kg0 + roff + 4 * u);
            CP16(vd + u * 16, vg0 + roff + 4 * u);
        }
    };

    issue(0, 0); CP_COMMIT();
    issue(1, 1); CP_COMMIT();

    // Q fragments, k16-split permutation: k8 step kk (grp=kk>>1, sub=kk&1)
    // uses physical d {grp*16 + 4fc + 2sub, +1}.
    uint32_t qa[8][4];
    {
        const float* q0 = qg + (size_t)(16 * w + fr) * EE;
#pragma unroll
        for (int kk = 0; kk < 8; kk++) {
            const int d = (kk >> 1) * 16 + 4 * fc + 2 * (kk & 1);
            qa[kk][0] = __float_as_uint(q0[d]);
            qa[kk][2] = __float_as_uint(q0[d + 1]);
            qa[kk][1] = __float_as_uint(q0[8 * (size_t)EE + d]);
            qa[kk][3] = __float_as_uint(q0[8 * (size_t)EE + d + 1]);
        }
    }

    float at[8][4];
    float o[8][4];
#pragma unroll
    for (int n = 0; n < 8; n++)
#pragma unroll
        for (int r = 0; r < 4; r++) at[n][r] = 0.f;
    float l0r = 0.f, l1r = 0.f;

    for (int g = 0; g < 64; g++) {
        if ((g & 15) == 0) {
            l0r = 0.f; l1r = 0.f;
#pragma unroll
            for (int n = 0; n < 8; n++)
#pragma unroll
                for (int r = 0; r < 4; r++) o[n][r] = 0.f;
        }
        if (g == 63) { CP_WAIT0(); } else { CP_WAIT1(); }
        __syncthreads();
        if (g + 2 < 64) { issue(g + 2, (g + 2) % 3); CP_COMMIT(); }

        const float* Kb = sm + (g % 3) * ASTG;
        const float* Vb = Kb + KSW;

        float s[8][4];
#pragma unroll
        for (int n = 0; n < 8; n++)
#pragma unroll
            for (int r = 0; r < 4; r++) s[n][r] = 0.f;

        // S = Q K^T : one float4 K load per (nf, d-group) feeds 2 MMAs
        const int kb0 = fr * KSTR + 4 * fc;
#pragma unroll
        for (int grp = 0; grp < 4; grp++) {
#pragma unroll
            for (int nf = 0; nf < 8; nf++) {
                float4 kb = *(const float4*)(Kb + nf * (8 * KSTR) + kb0 + grp * 16);
                mma_tf32(s[nf][0], s[nf][1], s[nf][2], s[nf][3],
                         qa[2 * grp][0], qa[2 * grp][1], qa[2 * grp][2], qa[2 * grp][3],
                         __float_as_uint(kb.x), __float_as_uint(kb.y));
                mma_tf32(s[nf][0], s[nf][1], s[nf][2], s[nf][3],
                         qa[2 * grp + 1][0], qa[2 * grp + 1][1], qa[2 * grp + 1][2], qa[2 * grp + 1][3],
                         __float_as_uint(kb.z), __float_as_uint(kb.w));
            }
        }

        // Max-free softmax in log2 domain: p = 2^s
        float sum0 = 0.f, sum1 = 0.f;
#pragma unroll
        for (int n = 0; n < 8; n++) {
            s[n][0] = exp2f(s[n][0]);
            s[n][1] = exp2f(s[n][1]);
            s[n][2] = exp2f(s[n][2]);
            s[n][3] = exp2f(s[n][3]);
            sum0 += s[n][0] + s[n][1];
            sum1 += s[n][2] + s[n][3];
        }
        sum0 += __shfl_xor_sync(0xffffffffu, sum0, 1);
        sum0 += __shfl_xor_sync(0xffffffffu, sum0, 2);
        sum1 += __shfl_xor_sync(0xffffffffu, sum1, 1);
        sum1 += __shfl_xor_sync(0xffffffffu, sum1, 2);
        l0r += sum0;
        l1r += sum1;

        // O += P V : accumulator fragment IS the A fragment (k {2fc,2fc+1})
        const int vb0 = 2 * fc * VSTR + fr;
#pragma unroll
        for (int j = 0; j < 8; j++) {
            const uint32_t a0 = tf32r(s[j][0]);
            const uint32_t a1 = tf32r(s[j][2]);
            const uint32_t a2 = tf32r(s[j][1]);
            const uint32_t a3 = tf32r(s[j][3]);
            const float* vp = Vb + j * (8 * VSTR) + vb0;
#pragma unroll
            for (int nf = 0; nf < 8; nf++) {
                mma_tf32(o[nf][0], o[nf][1], o[nf][2], o[nf][3],
                         a0, a1, a2, a3,
                         __float_as_uint(vp[8 * nf]), __float_as_uint(vp[VSTR + 8 * nf]));
            }
        }

        if ((g & 15) == 15) {
            const float inv0 = 0.25f / l0r;
            const float inv1 = 0.25f / l1r;
#pragma unroll
            for (int n = 0; n < 8; n++) {
                at[n][0] += o[n][0] * inv0;
                at[n][1] += o[n][1] * inv0;
                at[n][2] += o[n][2] * inv1;
                at[n][3] += o[n][3] * inv1;
            }
        }
    }

    // Write tf32-rounded (RNA) channel-pooled output (A operand of o_gemm)
    float* op = g_attn + (size_t)(b * TT + t0 + 16 * w + fr) * EE + h * DHD + 2 * fc;
#pragma unroll
    for (int nf = 0; nf < 8; nf++) {
        float2 v0, v1;
        v0.x = __uint_as_float(tf32r(at[nf][0]));
        v0.y = __uint_as_float(tf32r(at[nf][1]));
        v1.x = __uint_as_float(tf32r(at[nf][2]));
        v1.y = __uint_as_float(tf32r(at[nf][3]));
        *(float2*)(op + 8 * nf) = v0;
        *(float2*)(op + 8 * (size_t)EE + 8 * nf) = v1;
    }
}

// ---------------------------------------------------------------------------
extern "C" void kernel_launch(void* const* d_in, const int* in_sizes, int n_in,
                              void* d_out, int out_size)
{
    const float* hs = (const float*)d_in[0];
    const float* kv = (const float*)d_in[1];
    const float* Wq = (const float*)d_in[2];
    const float* bq = (const float*)d_in[3];
    const float* Wk = (const float*)d_in[4];
    const float* bk = (const float*)d_in[5];
    const float* Wv = (const float*)d_in[6];
    const float* bv = (const float*)d_in[7];
    const float* Wo = (const float*)d_in[8];
    const float* bo = (const float*)d_in[9];
    float* out = (float*)d_out;

    cudaFuncSetAttribute(qkv_gemm, cudaFuncAttributeMaxDynamicSharedMemorySize, GEMM_SMEM);
    cudaFuncSetAttribute(o_gemm, cudaFuncAttributeMaxDynamicSharedMemorySize, GEMM_SMEM);
    cudaFuncSetAttribute(attn_kernel, cudaFuncAttributeMaxDynamicSharedMemorySize, ATTN_SMEM);

    // tf32 (RNA) pre-rounding of inputs + weights
    preround<<<(F4_TOT + 255) / 256, 256>>>((const float4*)hs, (const float4*)kv,
                                            (const float4*)Wq, (const float4*)Wk,
                                            (const float4*)Wv, (const float4*)Wo);
    // Fused Q+K+V projections (Q scaled by Dh^-0.5 * log2e)
    qkv_gemm<<<1088, 128, GEMM_SMEM>>>(bq, bk, bv);
    // Flash attention with fused channel pooling -> g_attn
    attn_kernel<<<dim3(TT / 128, BB * HH), 256, ATTN_SMEM>>>();
    // Output projection: split-K x4 partials, then deterministic reduce + bias
    o_gemm<<<dim3(8, 8, 4), 128, GEMM_SMEM>>>();
    o_reduce<<<(BB * TT * EE / 4 + 255) / 256, 256>>>(bo, (float4*)out);
}